// round 8
// baseline (speedup 1.0000x reference)
#include <cuda_runtime.h>
#include <stdint.h>

// LengthRegulator, fused single-launch.
//   out[n, t, :] = x[n, searchsorted(csum[n], t, 'right'), :] for t < total[n], else 0
//   mel_pos = [1..T] appended after the frames.
//
// Output layout (validated via out_size divisibility, N*C = 24576):
//   case A: [ out: N*T*C f32 ][ mel_pos: T f32 ]
//   case B: [ out: N*T*C f32 ][ mel_pos: T i64 ]
//
// R8 changes vs R7 (45.1us):
//  - SLICES 16 -> 24: ~1.5 waves of shorter blocks so CTA spread backfills
//    instead of defining the kernel tail (one-wave spread cost ~1.1x).
//  - plain STG.128 instead of __stcs (R6 evidence: higher HBM throughput).
//  - software-pipelined gather: next frame's source float4 is loaded BEFORE
//    storing the current frame, hiding L2 latency at run transitions.

#define L_LEN    256
#define THREADS  288           // 3 frame-groups x 96 channel chunks
#define SLICES   24
#define FMAX     192           // max frames per block (T<=4096 -> fpb<=171)

__global__ __launch_bounds__(THREADS)
void lr_onewave_kernel(const float* __restrict__ x,
                       const int* __restrict__ dur,
                       float* __restrict__ out,
                       float* __restrict__ mp,
                       int T, int mel_is_i64)
{
    const int n    = blockIdx.x;
    const int s    = blockIdx.y;
    const int tid  = threadIdx.x;
    const int wid  = tid >> 5;
    const int lane = tid & 31;

    const int fpb     = (T + SLICES - 1) / SLICES;     // frames per block
    const int t_begin = s * fpb;
    const int t_end   = (t_begin + fpb < T) ? (t_begin + fpb) : T;
    const int nf      = t_end - t_begin;
    if (nf <= 0) return;

    __shared__ int csum[L_LEN];
    __shared__ int wsum[8];
    __shared__ int fidx[FMAX];

    // ---- mel_pos: row-0 blocks write their slice ----
    if (n == 0) {
        for (int f = tid; f < nf; f += THREADS) {
            int t = t_begin + f;
            if (mel_is_i64) ((long long*)mp)[t] = (long long)(t + 1);
            else            mp[t] = (float)(t + 1);
        }
    }

    // ---- inclusive prefix sum of durations (shuffle scan, warps 0..7) ----
    int v = 0;
    if (tid < L_LEN) {
        v = dur[n * L_LEN + tid];
        #pragma unroll
        for (int off = 1; off < 32; off <<= 1) {
            int u = __shfl_up_sync(0xFFFFFFFFu, v, off);
            if (lane >= off) v += u;
        }
        if (lane == 31) wsum[wid] = v;
    }
    __syncthreads();
    if (wid == 0 && lane < 8) {
        int t = wsum[lane];
        #pragma unroll
        for (int off = 1; off < 8; off <<= 1) {
            int u = __shfl_up_sync(0xFFu, t, off);
            if (lane >= off) t += u;
        }
        wsum[lane] = t;
    }
    __syncthreads();
    if (tid < L_LEN) csum[tid] = v + (wid > 0 ? wsum[wid - 1] : 0);
    __syncthreads();

    const int total = csum[L_LEN - 1];

    // ---- binary search source row for each frame of this chunk ----
    for (int f = tid; f < nf; f += THREADS) {
        int t  = t_begin + f;
        int id = -1;
        if (t < total) {
            int lo = 0, hi = L_LEN;
            while (lo < hi) {
                int mid = (lo + hi) >> 1;
                if (csum[mid] > t) hi = mid; else lo = mid + 1;
            }
            id = (lo < L_LEN) ? lo : (L_LEN - 1);
        }
        fidx[f] = id;
    }
    __syncthreads();

    // ---- streaming copy, software-pipelined source reload ----
    const int g = tid / 96;                // frame-group 0..2 (whole warps)
    const int c = tid - g * 96;            // channel chunk 0..95

    const int fpg = (nf + 2) / 3;
    const int f0  = g * fpg;
    const int f1  = (f0 + fpg < nf) ? (f0 + fpg) : nf;
    if (f0 >= f1) return;

    const float4* xv = (const float4*)(x + (size_t)n * L_LEN * 384);
    float4*       ov = (float4*)(out + ((size_t)n * T + t_begin) * 384) + c;
    const float4  z  = make_float4(0.f, 0.f, 0.f, 0.f);

    int    id  = fidx[f0];
    float4 val = (id >= 0) ? __ldg(&xv[(size_t)id * 96 + c]) : z;

    float4* dst = ov + (size_t)f0 * 96;
    for (int f = f0; f < f1; f++, dst += 96) {
        // peek next frame's id and start its load BEFORE storing current
        const int nid = (f + 1 < f1) ? fidx[f + 1] : id;
        float4 nval = val;
        if (nid != id)                      // warp-uniform branch
            nval = (nid >= 0) ? __ldg(&xv[(size_t)nid * 96 + c]) : z;
        dst[0] = val;
        val = nval;
        id  = nid;
    }
}

extern "C" void kernel_launch(void* const* d_in, const int* in_sizes, int n_in,
                              void* d_out, int out_size)
{
    const float* x   = (const float*)d_in[0];
    const int*   dur = (const int*)d_in[1];

    const int NL = in_sizes[1];            // N * L
    const int N  = NL / L_LEN;             // 64
    const int C  = in_sizes[0] / NL;       // 384 (layout assumes 384)

    const long long S    = (long long)out_size;
    const long long base = (long long)N * C;

    int T;
    int mel_is_i64 = 0;
    if (S % (base + 1) == 0) {
        T = (int)(S / (base + 1));         // case A: mel_pos as f32
    } else if (S % (base + 2) == 0) {
        T = (int)(S / (base + 2));         // case B: mel_pos as i64
        mel_is_i64 = 1;
    } else {
        T = (int)(S / base);               // fallback
    }

    float* out  = (float*)d_out;
    float* tail = out + (size_t)N * T * C;

    dim3 grid(N, SLICES);
    lr_onewave_kernel<<<grid, THREADS>>>(x, dur, out, tail, T, mel_is_i64);
}

// round 9
// speedup vs baseline: 1.2060x; 1.2060x over previous
#include <cuda_runtime.h>
#include <stdint.h>

// LengthRegulator, fused single-launch.
//   out[n, t, :] = x[n, searchsorted(csum[n], t, 'right'), :] for t < total[n], else 0
//   mel_pos = [1..T] appended after the frames.
//
// Output layout (validated via out_size divisibility, N*C = 24576):
//   case A: [ out: N*T*C f32 ][ mel_pos: T f32 ]
//   case B: [ out: N*T*C f32 ][ mel_pos: T i64 ]
//
// R9 = R7 prologue (fused, SLICES=16, proven 45.1us) + R6 copy-loop shape
// (proven best: 40.4us kernel @ DRAM 62%): ids batch-loaded into registers,
// fully unrolled 8-frame body, plain STG.128 so the compiler batches
// independent stores (store MLP). No __stcs, no per-frame LDS dependency.

#define L_LEN    256
#define THREADS  288           // 3 frame-groups x 96 channel chunks
#define SLICES   16
#define FMAX     272           // max frames per block (T<=4096 -> fpb<=256)

__global__ __launch_bounds__(THREADS)
void lr_onewave_kernel(const float* __restrict__ x,
                       const int* __restrict__ dur,
                       float* __restrict__ out,
                       float* __restrict__ mp,
                       int T, int mel_is_i64)
{
    const int n    = blockIdx.x;
    const int s    = blockIdx.y;
    const int tid  = threadIdx.x;
    const int wid  = tid >> 5;
    const int lane = tid & 31;

    const int fpb     = (T + SLICES - 1) / SLICES;     // frames per block
    const int t_begin = s * fpb;
    const int t_end   = (t_begin + fpb < T) ? (t_begin + fpb) : T;
    const int nf      = t_end - t_begin;
    if (nf <= 0) return;

    __shared__ int csum[L_LEN];
    __shared__ int wsum[8];
    __shared__ int fidx[FMAX];

    // ---- mel_pos: row-0 blocks write their slice ----
    if (n == 0) {
        for (int f = tid; f < nf; f += THREADS) {
            int t = t_begin + f;
            if (mel_is_i64) ((long long*)mp)[t] = (long long)(t + 1);
            else            mp[t] = (float)(t + 1);
        }
    }

    // ---- inclusive prefix sum of durations (shuffle scan, warps 0..7) ----
    int v = 0;
    if (tid < L_LEN) {
        v = dur[n * L_LEN + tid];
        #pragma unroll
        for (int off = 1; off < 32; off <<= 1) {
            int u = __shfl_up_sync(0xFFFFFFFFu, v, off);
            if (lane >= off) v += u;
        }
        if (lane == 31) wsum[wid] = v;
    }
    __syncthreads();
    if (wid == 0 && lane < 8) {
        int t = wsum[lane];
        #pragma unroll
        for (int off = 1; off < 8; off <<= 1) {
            int u = __shfl_up_sync(0xFFu, t, off);
            if (lane >= off) t += u;
        }
        wsum[lane] = t;
    }
    __syncthreads();
    if (tid < L_LEN) csum[tid] = v + (wid > 0 ? wsum[wid - 1] : 0);
    __syncthreads();

    const int total = csum[L_LEN - 1];

    // ---- binary search source row for each frame of this chunk ----
    for (int f = tid; f < nf; f += THREADS) {
        int t  = t_begin + f;
        int id = -1;
        if (t < total) {
            int lo = 0, hi = L_LEN;
            while (lo < hi) {
                int mid = (lo + hi) >> 1;
                if (csum[mid] > t) hi = mid; else lo = mid + 1;
            }
            id = (lo < L_LEN) ? lo : (L_LEN - 1);
        }
        fidx[f] = id;
    }
    __syncthreads();

    // ---- streaming copy: batch-of-8 frames, ids in registers, unrolled STGs ----
    const int g = tid / 96;                // frame-group 0..2 (whole warps)
    const int c = tid - g * 96;            // channel chunk 0..95

    const int fpg = (nf + 2) / 3;
    const int f0  = g * fpg;
    const int f1  = (f0 + fpg < nf) ? (f0 + fpg) : nf;
    if (f0 >= f1) return;

    const float4* xv = (const float4*)(x + (size_t)n * L_LEN * 384);
    float4*       ov = (float4*)(out + ((size_t)n * T + t_begin) * 384) + c;
    const float4  z  = make_float4(0.f, 0.f, 0.f, 0.f);

    int    cur = -2;
    float4 val = z;

    int f = f0;
    for (; f + 8 <= f1; f += 8) {
        // front-load the 8 ids (independent LDS, no per-store dependency)
        int ids[8];
        #pragma unroll
        for (int i = 0; i < 8; i++) ids[i] = fidx[f + i];

        float4 vals[8];
        #pragma unroll
        for (int i = 0; i < 8; i++) {
            if (ids[i] != cur) {           // warp-uniform
                val = (ids[i] >= 0) ? __ldg(&xv[(size_t)ids[i] * 96 + c]) : z;
                cur = ids[i];
            }
            vals[i] = val;
        }

        float4* dst = ov + (size_t)f * 96;
        #pragma unroll
        for (int i = 0; i < 8; i++)        // 8 independent STG.128
            dst[(size_t)i * 96] = vals[i];
    }
    // scalar tail
    for (; f < f1; f++) {
        const int id = fidx[f];
        if (id != cur) {
            val = (id >= 0) ? __ldg(&xv[(size_t)id * 96 + c]) : z;
            cur = id;
        }
        ov[(size_t)f * 96] = val;
    }
}

extern "C" void kernel_launch(void* const* d_in, const int* in_sizes, int n_in,
                              void* d_out, int out_size)
{
    const float* x   = (const float*)d_in[0];
    const int*   dur = (const int*)d_in[1];

    const int NL = in_sizes[1];            // N * L
    const int N  = NL / L_LEN;             // 64
    const int C  = in_sizes[0] / NL;       // 384 (layout assumes 384)

    const long long S    = (long long)out_size;
    const long long base = (long long)N * C;

    int T;
    int mel_is_i64 = 0;
    if (S % (base + 1) == 0) {
        T = (int)(S / (base + 1));         // case A: mel_pos as f32
    } else if (S % (base + 2) == 0) {
        T = (int)(S / (base + 2));         // case B: mel_pos as i64
        mel_is_i64 = 1;
    } else {
        T = (int)(S / base);               // fallback
    }

    float* out  = (float*)d_out;
    float* tail = out + (size_t)N * T * C;

    dim3 grid(N, SLICES);
    lr_onewave_kernel<<<grid, THREADS>>>(x, dur, out, tail, T, mel_is_i64);
}

// round 10
// speedup vs baseline: 1.3661x; 1.1328x over previous
#include <cuda_runtime.h>
#include <stdint.h>

// LengthRegulator, fused single-launch.
//   out[n, t, :] = x[n, searchsorted(csum[n], t, 'right'), :] for t < total[n], else 0
//   mel_pos = [1..T] appended after the frames.
//
// Output layout (validated via out_size divisibility, N*C = 24576):
//   case A: [ out: N*T*C f32 ][ mel_pos: T f32 ]
//   case B: [ out: N*T*C f32 ][ mel_pos: T i64 ]
//
// R10 = R5 grid layout (FRAMES=24, 6336 self-balancing blocks, single launch)
//     + R6 copy-loop shape (proven 40.4us @ 62% DRAM, 25 regs):
//       ids front-loaded into registers, then per frame: select source
//       (register-cached float4, warp-uniform reload) and store IMMEDIATELY.
//       No staging arrays (R9's regs=54 mistake), no per-iter bounds check
//       (full blocks take an unrolled path; only the tail block branches).

#define L_LEN    256
#define THREADS  288           // 3 frame-groups x 96 channel chunks
#define FRAMES   24
#define FPG      8

__global__ __launch_bounds__(THREADS)
void lr_fused_kernel(const float* __restrict__ x,
                     const int* __restrict__ dur,
                     float* __restrict__ out,
                     float* __restrict__ mp,
                     int T, int mel_is_i64)
{
    const int n    = blockIdx.y;
    const int t0   = blockIdx.x * FRAMES;
    const int tid  = threadIdx.x;
    const int wid  = tid >> 5;
    const int lane = tid & 31;

    __shared__ int csum[L_LEN];
    __shared__ int wsum[8];
    __shared__ int fidx[FRAMES];

    // ---- mel_pos: row-0 blocks write their 24 entries ----
    if (blockIdx.y == 0 && tid < FRAMES) {
        int t = t0 + tid;
        if (t < T) {
            if (mel_is_i64) ((long long*)mp)[t] = (long long)(t + 1);
            else            mp[t] = (float)(t + 1);
        }
    }

    // ---- inclusive prefix sum of durations (shuffle scan, warps 0..7) ----
    int v = 0;
    if (tid < L_LEN) {
        v = dur[n * L_LEN + tid];
        #pragma unroll
        for (int off = 1; off < 32; off <<= 1) {
            int u = __shfl_up_sync(0xFFFFFFFFu, v, off);
            if (lane >= off) v += u;
        }
        if (lane == 31) wsum[wid] = v;
    }
    __syncthreads();
    if (wid == 0 && lane < 8) {
        int s = wsum[lane];
        #pragma unroll
        for (int off = 1; off < 8; off <<= 1) {
            int u = __shfl_up_sync(0xFFu, s, off);
            if (lane >= off) s += u;
        }
        wsum[lane] = s;
    }
    __syncthreads();
    if (tid < L_LEN) csum[tid] = v + (wid > 0 ? wsum[wid - 1] : 0);
    __syncthreads();

    const int total = csum[L_LEN - 1];

    // ---- binary search source row for each of the 24 frames ----
    if (tid < FRAMES) {
        int t  = t0 + tid;
        int id = -1;
        if (t < T && t < total) {
            int lo = 0, hi = L_LEN;
            while (lo < hi) {
                int mid = (lo + hi) >> 1;
                if (csum[mid] > t) hi = mid; else lo = mid + 1;
            }
            id = (lo < L_LEN) ? lo : (L_LEN - 1);
        }
        fidx[tid] = id;
    }
    __syncthreads();

    // ---- streaming copy: R6 loop shape ----
    const int g = tid / 96;                // frame-group 0..2 (whole warps)
    const int c = tid - g * 96;            // channel chunk 0..95

    const float4* xv = (const float4*)(x + (size_t)n * L_LEN * 384);
    float4*       ov = (float4*)(out + ((size_t)n * T + t0) * 384) + c;
    const float4  z  = make_float4(0.f, 0.f, 0.f, 0.f);

    int    cur = -2;
    float4 val = z;
    const int fb = g * FPG;

    if (t0 + FRAMES <= T) {
        // full block: front-load 8 ids (two LDS.128), unrolled select+store
        const int4 ia = ((const int4*)fidx)[g * 2];
        const int4 ib = ((const int4*)fidx)[g * 2 + 1];
        const int ids[FPG] = { ia.x, ia.y, ia.z, ia.w, ib.x, ib.y, ib.z, ib.w };

        float4* dst = ov + (size_t)fb * 96;
        #pragma unroll
        for (int i = 0; i < FPG; i++) {
            const int id = ids[i];
            if (id != cur) {               // warp-uniform
                val = (id >= 0) ? __ldg(&xv[(size_t)id * 96 + c]) : z;
                cur = id;
            }
            dst[(size_t)i * 96] = val;     // immediate STG.128
        }
    } else {
        // tail block (at most one per row)
        for (int i = 0; i < FPG; i++) {
            const int f = fb + i;
            if (t0 + f >= T) break;
            const int id = fidx[f];
            if (id != cur) {
                val = (id >= 0) ? __ldg(&xv[(size_t)id * 96 + c]) : z;
                cur = id;
            }
            ov[(size_t)f * 96] = val;
        }
    }
}

extern "C" void kernel_launch(void* const* d_in, const int* in_sizes, int n_in,
                              void* d_out, int out_size)
{
    const float* x   = (const float*)d_in[0];
    const int*   dur = (const int*)d_in[1];

    const int NL = in_sizes[1];            // N * L
    const int N  = NL / L_LEN;             // 64
    const int C  = in_sizes[0] / NL;       // 384 (layout assumes 384)

    const long long S    = (long long)out_size;
    const long long base = (long long)N * C;

    int T;
    int mel_is_i64 = 0;
    if (S % (base + 1) == 0) {
        T = (int)(S / (base + 1));         // case A: mel_pos as f32
    } else if (S % (base + 2) == 0) {
        T = (int)(S / (base + 2));         // case B: mel_pos as i64
        mel_is_i64 = 1;
    } else {
        T = (int)(S / base);               // fallback
    }

    float* out  = (float*)d_out;
    float* tail = out + (size_t)N * T * C;

    dim3 grid((T + FRAMES - 1) / FRAMES, N);
    lr_fused_kernel<<<grid, THREADS>>>(x, dur, out, tail, T, mel_is_i64);
}